// round 6
// baseline (speedup 1.0000x reference)
#include <cuda_runtime.h>

#define NB 64
#define NH 16
#define TAU 1.0f

__device__ unsigned int g_segmax[NB * NH];  // float bits; all >= 0 (post-ReLU)
__device__ float g_gate[NB];

// ---------- kernels ----------
__global__ void init_kernel() {
    int i = threadIdx.x;
    if (i < NB * NH) g_segmax[i] = 0u;
}

// Scalar f32, 1 point per thread. ~55 live regs -> no spills, high occupancy.
__global__ __launch_bounds__(256, 4) void mlp_seg_kernel(
    const float* __restrict__ pos, const float* __restrict__ refl,
    const int* __restrict__ batch,
    const float* __restrict__ W1, const float* __restrict__ b1,
    const float* __restrict__ W2, const float* __restrict__ b2,
    int n)
{
    // Weights in shared, rows chunked as float4 for LDS.128 broadcasts.
    __shared__ float4 sW1[16];   // W1[k][j]: sW1[k*4+q] = W1 row k, cols 4q..4q+3
    __shared__ float4 sW2[64];   // W2[k][j]: sW2[k*4+q]
    __shared__ float  sB1[16];
    __shared__ float  sB2[16];

    {
        int i = threadIdx.x;
        if (i < 16)  sW1[i] = reinterpret_cast<const float4*>(W1)[i];
        else if (i < 80) sW2[i - 16] = reinterpret_cast<const float4*>(W2)[i - 16];
        else if (i < 96) sB1[i - 80] = b1[i - 80];
        else if (i < 112) sB2[i - 96] = b2[i - 96];
    }
    __syncthreads();

    const int t = blockIdx.x * blockDim.x + threadIdx.x;
    const bool valid = (t < n);
    const int lane = threadIdx.x & 31;

    float f0 = 0.f, f1 = 0.f, f2 = 0.f, f3 = 0.f;
    int seg = 0;
    if (valid) {
        f0 = pos[3 * t + 0];
        f1 = pos[3 * t + 1];
        f2 = pos[3 * t + 2];
        f3 = refl[t];
        seg = batch[t];
    }

    // layer 1: [4] -> [16]
    float a[NH];
    #pragma unroll
    for (int q = 0; q < 4; q++) {
        float4 w0 = sW1[0 * 4 + q];
        float4 w1 = sW1[1 * 4 + q];
        float4 w2 = sW1[2 * 4 + q];
        float4 w3 = sW1[3 * 4 + q];
        a[4 * q + 0] = fmaxf(sB1[4 * q + 0] + f0 * w0.x + f1 * w1.x + f2 * w2.x + f3 * w3.x, 0.f);
        a[4 * q + 1] = fmaxf(sB1[4 * q + 1] + f0 * w0.y + f1 * w1.y + f2 * w2.y + f3 * w3.y, 0.f);
        a[4 * q + 2] = fmaxf(sB1[4 * q + 2] + f0 * w0.z + f1 * w1.z + f2 * w2.z + f3 * w3.z, 0.f);
        a[4 * q + 3] = fmaxf(sB1[4 * q + 3] + f0 * w0.w + f1 * w1.w + f2 * w2.w + f3 * w3.w, 0.f);
    }

    // layer 2: [16] -> [16]
    float c[NH];
    #pragma unroll
    for (int j = 0; j < NH; j++) c[j] = sB2[j];
    #pragma unroll
    for (int k = 0; k < NH; k++) {
        float ak = a[k];
        #pragma unroll
        for (int q = 0; q < 4; q++) {
            float4 w = sW2[k * 4 + q];
            c[4 * q + 0] += ak * w.x;
            c[4 * q + 1] += ak * w.y;
            c[4 * q + 2] += ak * w.z;
            c[4 * q + 3] += ak * w.w;
        }
    }

    // warp-uniform segment check (batch sorted)
    const int  wseg = __shfl_sync(0xffffffffu, seg, 0);
    const bool wuni = __all_sync(0xffffffffu, valid && (seg == wseg));

    if (wuni) {
        // relu folded into max(.,0); one REDUX + lane-0 atomic per feature
        #pragma unroll
        for (int j = 0; j < NH; j++) {
            float m = fmaxf(c[j], 0.0f);
            unsigned um = __reduce_max_sync(0xffffffffu, __float_as_uint(m));
            if (lane == 0)
                atomicMax(&g_segmax[wseg * NH + j], um);
        }
    } else if (valid) {
        // boundary / partial warps: per-point atomics
        #pragma unroll
        for (int j = 0; j < NH; j++)
            atomicMax(&g_segmax[seg * NH + j],
                      __float_as_uint(fmaxf(c[j], 0.0f)));
    }
}

__global__ void gate_kernel(const float* __restrict__ Wg,
                            const float* __restrict__ bg,
                            const float* __restrict__ gumbels)
{
    int b = threadIdx.x;
    if (b < NB) {
        float l0 = bg[0] + gumbels[2 * b + 0];
        float l1 = bg[1] + gumbels[2 * b + 1];
        #pragma unroll
        for (int k = 0; k < NH; k++) {
            float sf = __uint_as_float(g_segmax[b * NH + k]);
            l0 += sf * Wg[2 * k + 0];
            l1 += sf * Wg[2 * k + 1];
        }
        l0 *= (1.0f / TAU);
        l1 *= (1.0f / TAU);
        float m = fmaxf(l0, l1);
        float e0 = expf(l0 - m);
        float e1 = expf(l1 - m);
        g_gate[b] = e1 / (e0 + e1);
    }
}

__global__ __launch_bounds__(256) void scale_kernel(
    const float* __restrict__ refl, const int* __restrict__ batch,
    float* __restrict__ out, int n)
{
    __shared__ float sg[NB];
    if (threadIdx.x < NB) sg[threadIdx.x] = g_gate[threadIdx.x];
    __syncthreads();

    const int t = blockIdx.x * blockDim.x + threadIdx.x;
    const long base = 4L * t;
    if (base + 3 < (long)n) {
        float4 r = reinterpret_cast<const float4*>(refl)[t];
        int4 b = reinterpret_cast<const int4*>(batch)[t];
        float4 o;
        o.x = sg[b.x] * r.x;
        o.y = sg[b.y] * r.y;
        o.z = sg[b.z] * r.z;
        o.w = sg[b.w] * r.w;
        reinterpret_cast<float4*>(out)[t] = o;
    } else {
        for (long p = base; p < (long)n; ++p) out[p] = sg[batch[p]] * refl[p];
    }
}

extern "C" void kernel_launch(void* const* d_in, const int* in_sizes, int n_in,
                              void* d_out, int out_size)
{
    const float* pos     = (const float*)d_in[0];
    const float* refl    = (const float*)d_in[1];
    const int*   batch   = (const int*)d_in[2];
    const float* gumbels = (const float*)d_in[3];
    const float* W1      = (const float*)d_in[4];
    const float* b1      = (const float*)d_in[5];
    const float* W2      = (const float*)d_in[6];
    const float* b2      = (const float*)d_in[7];
    const float* Wg      = (const float*)d_in[8];
    const float* bg      = (const float*)d_in[9];
    float* out = (float*)d_out;

    const int n = in_sizes[1];  // N
    const int mlp_blocks   = (n + 255) / 256;    // 1 point per thread
    const int scale_blocks = (n + 1023) / 1024;  // 4 points per thread

    init_kernel<<<1, NB * NH>>>();
    mlp_seg_kernel<<<mlp_blocks, 256>>>(pos, refl, batch, W1, b1, W2, b2, n);
    gate_kernel<<<1, NB>>>(Wg, bg, gumbels);
    scale_kernel<<<scale_blocks, 256>>>(refl, batch, out, n);
}

// round 8
// speedup vs baseline: 11.0563x; 11.0563x over previous
#include <cuda_runtime.h>

#define NB 64
#define NH 16
#define TAU 1.0f

__device__ unsigned int g_segmax[NB * NH];  // float bits; all >= 0 (post-ReLU)
__device__ float g_gate[NB];

// ---------- packed f32x2 helpers ----------
__device__ __forceinline__ unsigned long long pack2(float lo, float hi) {
    unsigned long long r;
    asm("mov.b64 %0, {%1, %2};" : "=l"(r) : "f"(lo), "f"(hi));
    return r;
}
__device__ __forceinline__ float2 unpack2(unsigned long long p) {
    float2 f;
    asm("mov.b64 {%0, %1}, %2;" : "=f"(f.x), "=f"(f.y) : "l"(p));
    return f;
}
__device__ __forceinline__ unsigned long long fma2(unsigned long long a,
                                                   unsigned long long b,
                                                   unsigned long long c) {
    unsigned long long d;
    asm("fma.rn.f32x2 %0, %1, %2, %3;" : "=l"(d) : "l"(a), "l"(b), "l"(c));
    return d;
}
__device__ __forceinline__ unsigned long long relu2(unsigned long long p) {
    float2 f = unpack2(p);
    return pack2(fmaxf(f.x, 0.0f), fmaxf(f.y, 0.0f));
}
__device__ __forceinline__ float lo2(unsigned long long p) { return unpack2(p).x; }

// ---------- kernels ----------
__global__ void init_kernel() {
    int i = threadIdx.x;
    if (i < NB * NH) g_segmax[i] = 0u;
}

__global__ void dummyA_kernel() {}
__global__ void dummyB_kernel() {}

__global__ __launch_bounds__(256, 2) void mlp_seg_kernel(
    const float* __restrict__ pos, const float* __restrict__ refl,
    const int* __restrict__ batch,
    const float* __restrict__ W1, const float* __restrict__ b1,
    const float* __restrict__ W2, const float* __restrict__ b2,
    int n)
{
    // weights pre-duplicated into b64 pairs so one LDS.64 feeds both packed halves
    __shared__ unsigned long long sW1[4 * NH];
    __shared__ unsigned long long sB1[NH];
    __shared__ unsigned long long sW2[NH * NH];
    __shared__ unsigned long long sB2[NH];

    for (int i = threadIdx.x; i < 4 * NH + NH + NH * NH + NH; i += blockDim.x) {
        float w;
        if (i < 64)       { w = W1[i];       sW1[i]       = pack2(w, w); }
        else if (i < 80)  { w = b1[i - 64];  sB1[i - 64]  = pack2(w, w); }
        else if (i < 336) { w = W2[i - 80];  sW2[i - 80]  = pack2(w, w); }
        else              { w = b2[i - 336]; sB2[i - 336] = pack2(w, w); }
    }
    __syncthreads();

    const int t = blockIdx.x * blockDim.x + threadIdx.x;
    const long base = 4L * t;
    const bool full4 = (base + 3 < (long)n);
    const int lane = threadIdx.x & 31;

    if (!full4) {
        // tail: fully scalar (usually never taken: N % 4 == 0)
        for (long p = base; p < (long)n; ++p) {
            float f[4] = {pos[3 * p + 0], pos[3 * p + 1], pos[3 * p + 2], refl[p]};
            float h1[NH];
            #pragma unroll
            for (int j = 0; j < NH; j++) {
                float s = lo2(sB1[j]);
                #pragma unroll
                for (int k = 0; k < 4; k++) s += f[k] * lo2(sW1[k * NH + j]);
                h1[j] = fmaxf(s, 0.0f);
            }
            int sgi = batch[p];
            #pragma unroll
            for (int j = 0; j < NH; j++) {
                float s = lo2(sB2[j]);
                #pragma unroll
                for (int k = 0; k < NH; k++) s += h1[k] * lo2(sW2[k * NH + j]);
                s = fmaxf(s, 0.0f);
                atomicMax(&g_segmax[sgi * NH + j], __float_as_uint(s));
            }
        }
        return;
    }

    const float4* pos4 = reinterpret_cast<const float4*>(pos);
    float4 v0 = pos4[3 * t + 0];
    float4 v1 = pos4[3 * t + 1];
    float4 v2 = pos4[3 * t + 2];
    float4 r  = reinterpret_cast<const float4*>(refl)[t];
    int4  bb  = reinterpret_cast<const int4*>(batch)[t];

    // warp-uniform segment check (batch sorted: bb.x == bb.w => all 4 equal)
    const int  wseg = __shfl_sync(0xffffffffu, bb.x, 0);
    const bool wuni = __all_sync(0xffffffffu, (bb.x == bb.w) && (bb.x == wseg));

    // features packed across point pairs: pair0=(p0,p1), pair1=(p2,p3)
    unsigned long long f0[4], f1[4];
    f0[0] = pack2(v0.x, v0.w); f0[1] = pack2(v0.y, v1.x);
    f0[2] = pack2(v0.z, v1.y); f0[3] = pack2(r.x,  r.y);
    f1[0] = pack2(v1.z, v2.y); f1[1] = pack2(v1.w, v2.z);
    f1[2] = pack2(v2.x, v2.w); f1[3] = pack2(r.z,  r.w);

    // layer 1: [4] -> [16], both pairs
    unsigned long long a0[NH], a1[NH];
    #pragma unroll
    for (int j = 0; j < NH; j++) { a0[j] = sB1[j]; a1[j] = sB1[j]; }
    #pragma unroll
    for (int k = 0; k < 4; k++) {
        #pragma unroll
        for (int j = 0; j < NH; j++) {
            unsigned long long w = sW1[k * NH + j];
            a0[j] = fma2(f0[k], w, a0[j]);
            a1[j] = fma2(f1[k], w, a1[j]);
        }
    }
    #pragma unroll
    for (int j = 0; j < NH; j++) { a0[j] = relu2(a0[j]); a1[j] = relu2(a1[j]); }

    // layer 2 in j-quarters to bound live registers: only c0[4],c1[4] live at once
    if (wuni) {
        unsigned keep = 0u;  // lane j holds the warp-max of feature j (j = lane, <16)
        #pragma unroll
        for (int q = 0; q < 4; q++) {
            unsigned long long c0[4], c1[4];
            #pragma unroll
            for (int j = 0; j < 4; j++) { c0[j] = sB2[q * 4 + j]; c1[j] = c0[j]; }
            #pragma unroll
            for (int k = 0; k < NH; k++) {
                #pragma unroll
                for (int j = 0; j < 4; j++) {
                    unsigned long long w = sW2[k * NH + q * 4 + j];
                    c0[j] = fma2(a0[k], w, c0[j]);
                    c1[j] = fma2(a1[k], w, c1[j]);
                }
            }
            #pragma unroll
            for (int j = 0; j < 4; j++) {
                // relu folded into the max-with-0
                float2 x = unpack2(c0[j]);
                float2 y = unpack2(c1[j]);
                float m = fmaxf(fmaxf(fmaxf(x.x, x.y), fmaxf(y.x, y.y)), 0.0f);
                unsigned um = __reduce_max_sync(0xffffffffu, __float_as_uint(m));
                if (lane == q * 4 + j) keep = um;
            }
        }
        // one RED per lane, 16 lanes in parallel (instead of 16 serial from lane 0)
        if (lane < NH)
            atomicMax(&g_segmax[wseg * NH + lane], keep);
    } else {
        // rare: segment boundary inside this warp — per-point atomics
        int segs[4] = {bb.x, bb.y, bb.z, bb.w};
        #pragma unroll
        for (int q = 0; q < 4; q++) {
            unsigned long long c0[4], c1[4];
            #pragma unroll
            for (int j = 0; j < 4; j++) { c0[j] = sB2[q * 4 + j]; c1[j] = c0[j]; }
            #pragma unroll
            for (int k = 0; k < NH; k++) {
                #pragma unroll
                for (int j = 0; j < 4; j++) {
                    unsigned long long w = sW2[k * NH + q * 4 + j];
                    c0[j] = fma2(a0[k], w, c0[j]);
                    c1[j] = fma2(a1[k], w, c1[j]);
                }
            }
            #pragma unroll
            for (int j = 0; j < 4; j++) {
                float2 x = unpack2(c0[j]);
                float2 y = unpack2(c1[j]);
                float v[4] = {fmaxf(x.x, 0.0f), fmaxf(x.y, 0.0f),
                              fmaxf(y.x, 0.0f), fmaxf(y.y, 0.0f)};
                #pragma unroll
                for (int p = 0; p < 4; p++)
                    atomicMax(&g_segmax[segs[p] * NH + q * 4 + j], __float_as_uint(v[p]));
            }
        }
    }
}

__global__ void gate_kernel(const float* __restrict__ Wg,
                            const float* __restrict__ bg,
                            const float* __restrict__ gumbels)
{
    int b = threadIdx.x;
    if (b < NB) {
        float l0 = bg[0] + gumbels[2 * b + 0];
        float l1 = bg[1] + gumbels[2 * b + 1];
        #pragma unroll
        for (int k = 0; k < NH; k++) {
            float sf = __uint_as_float(g_segmax[b * NH + k]);
            l0 += sf * Wg[2 * k + 0];
            l1 += sf * Wg[2 * k + 1];
        }
        l0 *= (1.0f / TAU);
        l1 *= (1.0f / TAU);
        float m = fmaxf(l0, l1);
        float e0 = expf(l0 - m);
        float e1 = expf(l1 - m);
        g_gate[b] = e1 / (e0 + e1);
    }
}

__global__ __launch_bounds__(256) void scale_kernel(
    const float* __restrict__ refl, const int* __restrict__ batch,
    float* __restrict__ out, int n)
{
    __shared__ float sg[NB];
    if (threadIdx.x < NB) sg[threadIdx.x] = g_gate[threadIdx.x];
    __syncthreads();

    const int t = blockIdx.x * blockDim.x + threadIdx.x;
    const long base = 4L * t;
    if (base + 3 < (long)n) {
        float4 r = reinterpret_cast<const float4*>(refl)[t];
        int4 b = reinterpret_cast<const int4*>(batch)[t];
        float4 o;
        o.x = sg[b.x] * r.x;
        o.y = sg[b.y] * r.y;
        o.z = sg[b.z] * r.z;
        o.w = sg[b.w] * r.w;
        reinterpret_cast<float4*>(out)[t] = o;
    } else {
        for (long p = base; p < (long)n; ++p) out[p] = sg[batch[p]] * refl[p];
    }
}

extern "C" void kernel_launch(void* const* d_in, const int* in_sizes, int n_in,
                              void* d_out, int out_size)
{
    const float* pos     = (const float*)d_in[0];
    const float* refl    = (const float*)d_in[1];
    const int*   batch   = (const int*)d_in[2];
    const float* gumbels = (const float*)d_in[3];
    const float* W1      = (const float*)d_in[4];
    const float* b1      = (const float*)d_in[5];
    const float* W2      = (const float*)d_in[6];
    const float* b2      = (const float*)d_in[7];
    const float* Wg      = (const float*)d_in[8];
    const float* bg      = (const float*)d_in[9];
    float* out = (float*)d_out;

    const int n = in_sizes[1];  // N
    const int blocks = (n + 1023) / 1024;  // 256 threads x 4 points

    // mlp is made the 4th user launch so ncu (-s 5 -c 1) captures it
    init_kernel<<<1, NB * NH>>>();
    dummyA_kernel<<<1, 32>>>();
    dummyB_kernel<<<1, 32>>>();
    mlp_seg_kernel<<<blocks, 256>>>(pos, refl, batch, W1, b1, W2, b2, n);
    gate_kernel<<<1, NB>>>(Wg, bg, gumbels);
    scale_kernel<<<blocks, 256>>>(refl, batch, out, n);
}